// round 1
// baseline (speedup 1.0000x reference)
#include <cuda_runtime.h>
#include <cstdint>

// Problem constants
#define T_STEPS 16384
#define HID     2048
#define IN_SZ   512
#define OUT_SZ  512
#define WH_LD   2560      // HID + IN_SZ
#define NBLK    128       // CTAs in recurrence kernel
#define RPB     16        // rows of h per CTA (NBLK*RPB == HID)

// ---------------------------------------------------------------------------
// Scratch (device globals — no allocation allowed)
// ---------------------------------------------------------------------------
__device__ float  g_pre[(size_t)T_STEPS * HID];   // 128 MB: Wx@x_t + bh
__device__ float  g_H  [(size_t)T_STEPS * HID];   // 128 MB: h_t for output GEMM
__device__ float2 g_hbuf[2][HID];                 // (value, step-tag) broadcast buffers

// ---------------------------------------------------------------------------
// Helpers
// ---------------------------------------------------------------------------
__device__ __forceinline__ float4 ldcv4(const float4* p) {
    float4 v;
    asm volatile("ld.global.cv.v4.f32 {%0,%1,%2,%3},[%4];"
                 : "=f"(v.x), "=f"(v.y), "=f"(v.z), "=f"(v.w)
                 : "l"(p));
    return v;
}
__device__ __forceinline__ void stcg2(float2* p, float a, float b) {
    asm volatile("st.global.cg.v2.f32 [%0],{%1,%2};"
                 :: "l"(p), "f"(a), "f"(b) : "memory");
}

// ---------------------------------------------------------------------------
// Init: seed h_0 with tag 0, invalidate the other parity buffer.
// Must run every launch (resets stale tags from previous graph replays).
// ---------------------------------------------------------------------------
__global__ void init_kernel(const float* __restrict__ h0) {
    int i = blockIdx.x * blockDim.x + threadIdx.x;
    if (i < HID) {
        g_hbuf[0][i] = make_float2(h0[i], __int_as_float(0));
        g_hbuf[1][i] = make_float2(0.f,   __int_as_float(-1));
    }
}

// ---------------------------------------------------------------------------
// Generic fp32 SGEMM with bias:  C[m][n] = bias[n] + sum_k A[m][k]*B[n][k]
// BM=BN=128, BK=8, 256 threads, 8x8 per thread. All dims divide evenly here.
// ---------------------------------------------------------------------------
__global__ __launch_bounds__(256) void sgemm_bias(
    const float* __restrict__ A, int lda,
    const float* __restrict__ B, int ldb,
    const float* __restrict__ bias,
    float* __restrict__ C, int ldc, int K)
{
    __shared__ float As[8][128];
    __shared__ float Bs[8][128];
    const int tid  = threadIdx.x;
    const size_t m0 = (size_t)blockIdx.y * 128;
    const int n0   = blockIdx.x * 128;
    const int lrow = tid >> 1;
    const int lc4  = (tid & 1) * 4;
    const int tx   = tid & 15, ty = tid >> 4;

    const float* Ap = A + (m0 + lrow) * (size_t)lda + lc4;
    const float* Bp = B + ((size_t)(n0 + lrow)) * (size_t)ldb + lc4;

    float acc[8][8];
    #pragma unroll
    for (int i = 0; i < 8; i++)
        #pragma unroll
        for (int j = 0; j < 8; j++) acc[i][j] = 0.f;

    for (int k0 = 0; k0 < K; k0 += 8) {
        float4 a4 = *(const float4*)(Ap + k0);
        float4 b4 = *(const float4*)(Bp + k0);
        __syncthreads();
        As[lc4+0][lrow] = a4.x; As[lc4+1][lrow] = a4.y;
        As[lc4+2][lrow] = a4.z; As[lc4+3][lrow] = a4.w;
        Bs[lc4+0][lrow] = b4.x; Bs[lc4+1][lrow] = b4.y;
        Bs[lc4+2][lrow] = b4.z; Bs[lc4+3][lrow] = b4.w;
        __syncthreads();
        #pragma unroll
        for (int kk = 0; kk < 8; kk++) {
            float ar[8], br[8];
            *(float4*)&ar[0] = *(const float4*)&As[kk][ty*8];
            *(float4*)&ar[4] = *(const float4*)&As[kk][ty*8+4];
            *(float4*)&br[0] = *(const float4*)&Bs[kk][tx*8];
            *(float4*)&br[4] = *(const float4*)&Bs[kk][tx*8+4];
            #pragma unroll
            for (int i = 0; i < 8; i++)
                #pragma unroll
                for (int j = 0; j < 8; j++)
                    acc[i][j] = fmaf(ar[i], br[j], acc[i][j]);
        }
    }

    float bv[8];
    *(float4*)&bv[0] = *(const float4*)&bias[n0 + tx*8];
    *(float4*)&bv[4] = *(const float4*)&bias[n0 + tx*8 + 4];
    #pragma unroll
    for (int i = 0; i < 8; i++) {
        size_t crow = m0 + ty*8 + i;
        float4 o0 = make_float4(acc[i][0]+bv[0], acc[i][1]+bv[1],
                                acc[i][2]+bv[2], acc[i][3]+bv[3]);
        float4 o1 = make_float4(acc[i][4]+bv[4], acc[i][5]+bv[5],
                                acc[i][6]+bv[6], acc[i][7]+bv[7]);
        *(float4*)&C[crow * (size_t)ldc + n0 + tx*8]     = o0;
        *(float4*)&C[crow * (size_t)ldc + n0 + tx*8 + 4] = o1;
    }
}

// ---------------------------------------------------------------------------
// Persistent recurrence kernel. 128 CTAs x 512 threads, all co-resident.
// CTA b owns h-rows [16b, 16b+16). Whh slice lives in REGISTERS (16 float4
// per lane = 16 MB chip-wide). Warp w covers columns [128w, 128w+128);
// lane l covers columns c0 = 128w+4l .. c0+3.
// Sync is data-flow only: (value, tag) pairs polled with ld.global.cv.
// ---------------------------------------------------------------------------
__global__ __launch_bounds__(512, 1) void rnn_kernel(const float* __restrict__ Wh)
{
    const int tid  = threadIdx.x;
    const int w    = tid >> 5;
    const int l    = tid & 31;
    const int row0 = blockIdx.x * RPB;
    const int c0   = w * 128 + l * 4;

    // Load this lane's Whh slice into registers (hidden part = cols 512..2559)
    float4 wreg[RPB];
    #pragma unroll
    for (int r = 0; r < RPB; r++)
        wreg[r] = *(const float4*)&Wh[(size_t)(row0 + r) * WH_LD + IN_SZ + c0];

    __shared__ float sred[2][RPB * 16];   // [parity][row*16 + warp]

    const float4* hb0 = (const float4*)&g_hbuf[0][0];
    const float4* hb1 = (const float4*)&g_hbuf[1][0];
    const int pairIdx = c0 >> 1;          // float4 index: covers cols c0,c0+1

    for (int t = 1; t <= T_STEPS; t++) {
        // Prefetch pre-activation for my rows (independent of h)
        float pre = 0.f;
        if (tid < RPB)
            pre = g_pre[(size_t)(t - 1) * HID + row0 + tid];

        // ---- poll for h_{t-1} (my 4 columns) ----
        const float4* src = ((t - 1) & 1) ? hb1 : hb0;
        const int tag = t - 1;
        float4 p0, p1;
        bool r0 = false, r1 = false;
        do {
            if (!r0) {
                p0 = ldcv4(src + pairIdx);
                r0 = (__float_as_int(p0.y) == tag) && (__float_as_int(p0.w) == tag);
            }
            if (!r1) {
                p1 = ldcv4(src + pairIdx + 1);
                r1 = (__float_as_int(p1.y) == tag) && (__float_as_int(p1.w) == tag);
            }
        } while (!(r0 && r1));
        const float h0 = p0.x, h1 = p0.z, h2 = p1.x, h3 = p1.z;

        // ---- partial dot products: 16 rows x my 4 columns ----
        float v[RPB];
        #pragma unroll
        for (int r = 0; r < RPB; r++) {
            float s = wreg[r].x * h0;
            s = fmaf(wreg[r].y, h1, s);
            s = fmaf(wreg[r].z, h2, s);
            s = fmaf(wreg[r].w, h3, s);
            v[r] = s;
        }

        // ---- packed butterfly: reduce 16 values across 32 lanes (16 SHFL) ----
        {
            const bool hi = (l & 16);
            #pragma unroll
            for (int i = 0; i < 8; i++) {
                float keep = hi ? v[i+8] : v[i];
                float send = hi ? v[i]   : v[i+8];
                v[i] = keep + __shfl_xor_sync(0xffffffffu, send, 16);
            }
        }
        {
            const bool hi = (l & 8);
            #pragma unroll
            for (int i = 0; i < 4; i++) {
                float keep = hi ? v[i+4] : v[i];
                float send = hi ? v[i]   : v[i+4];
                v[i] = keep + __shfl_xor_sync(0xffffffffu, send, 8);
            }
        }
        {
            const bool hi = (l & 4);
            #pragma unroll
            for (int i = 0; i < 2; i++) {
                float keep = hi ? v[i+2] : v[i];
                float send = hi ? v[i]   : v[i+2];
                v[i] = keep + __shfl_xor_sync(0xffffffffu, send, 4);
            }
        }
        {
            const bool hi = (l & 2);
            float keep = hi ? v[1] : v[0];
            float send = hi ? v[0] : v[1];
            v[0] = keep + __shfl_xor_sync(0xffffffffu, send, 2);
        }
        v[0] += __shfl_xor_sync(0xffffffffu, v[0], 1);
        // lane L (even) now holds stripe-sum of row index (L>>1)&15

        const int par = t & 1;
        if (!(l & 1))
            sred[par][(((l >> 1) & 15) << 4) | w] = v[0];
        __syncthreads();

        // ---- final cross-warp reduce + tanh + publish (warp 0, lanes 0..15)
        if (tid < RPB) {
            float s = pre;
            #pragma unroll
            for (int ww = 0; ww < 16; ww++)
                s += sred[par][(tid << 4) | ww];
            float h = tanhf(s);
            g_H[(size_t)(t - 1) * HID + row0 + tid] = h;
            stcg2(&g_hbuf[par][row0 + tid], h, __int_as_float(t));
        }
        // No trailing barrier needed: sred is parity double-buffered, and a
        // warp can only reach parity p again after ALL CTAs consumed h_t,
        // which requires this warp's publish above to have completed.
    }
}

// ---------------------------------------------------------------------------
// Launch
// ---------------------------------------------------------------------------
extern "C" void kernel_launch(void* const* d_in, const int* in_sizes, int n_in,
                              void* d_out, int out_size)
{
    const float* x   = (const float*)d_in[0];  // [16384, 512]
    const float* h0  = (const float*)d_in[1];  // [2048]
    const float* Wh  = (const float*)d_in[2];  // [2048, 2560]
    const float* bh  = (const float*)d_in[3];  // [2048]
    const float* Wo  = (const float*)d_in[4];  // [512, 2048]
    const float* bo  = (const float*)d_in[5];  // [512]
    float* out = (float*)d_out;                // [16384, 512]

    float* pre = nullptr;
    float* H   = nullptr;
    cudaGetSymbolAddress((void**)&pre, g_pre);
    cudaGetSymbolAddress((void**)&H,   g_H);

    // Reset tags + seed h_0 (every launch — clears stale tags between replays)
    init_kernel<<<(HID + 255) / 256, 256>>>(h0);

    // PRE = X @ Wx^T + bh   (Wx = Wh[:, :512], row stride 2560)
    sgemm_bias<<<dim3(HID / 128, T_STEPS / 128), 256>>>(
        x, IN_SZ, Wh, WH_LD, bh, pre, HID, IN_SZ);

    // Sequential recurrence (persistent, data-flow synced)
    rnn_kernel<<<NBLK, 512>>>(Wh);

    // OUT = H @ Wo^T + bo
    sgemm_bias<<<dim3(OUT_SZ / 128, T_STEPS / 128), 256>>>(
        H, HID, Wo, HID, bo, out, OUT_SZ, HID);
}